// round 15
// baseline (speedup 1.0000x reference)
#include <cuda_runtime.h>
#include <cuda_fp16.h>
#include <cstdint>

#define NPTS 16384
#define MP   4096
#define KNB  16

// ---------------- helpers ----------------
__device__ __forceinline__ uint32_t s2u(const void* p) {
    uint32_t a;
    asm("{ .reg .u64 t; cvta.to.shared.u64 t, %1; cvt.u32.u64 %0, t; }" : "=r"(a) : "l"(p));
    return a;
}
#define CP16(dst, src) asm volatile("cp.async.cg.shared.global [%0], [%1], 16;" :: "r"(dst), "l"(src))
#define CP_COMMIT()    asm volatile("cp.async.commit_group;" ::: "memory")
#define CP_WAIT0()     asm volatile("cp.async.wait_group 0;" ::: "memory")
#define CP_WAIT1()     asm volatile("cp.async.wait_group 1;" ::: "memory")

__device__ __forceinline__ uint32_t tile_off(int r, int c16) {
    return (uint32_t)(r * 256 + ((c16 ^ (r & 7)) << 4));
}
template <int NT>
__device__ __forceinline__ void fill_tile_async(uint32_t dst, const __half* __restrict__ src, int tid) {
#pragma unroll
    for (int it = 0; it < 2048 / NT; it++) {
        int idx = tid + it * NT;
        int r = idx >> 4, c16 = idx & 15;
        CP16(dst + tile_off(r, c16), src + r * 128 + c16 * 8);
    }
}
__device__ __forceinline__ void ldmA(uint32_t* a, uint32_t base, int mrow, int kcol, int lane) {
    uint32_t addr = base + tile_off(mrow + (lane & 15), (kcol >> 3) + (lane >> 4));
    asm volatile("ldmatrix.sync.aligned.m8n8.x4.shared.b16 {%0,%1,%2,%3}, [%4];"
        : "=r"(a[0]), "=r"(a[1]), "=r"(a[2]), "=r"(a[3]) : "r"(addr));
}
__device__ __forceinline__ void ldmB(uint32_t* b, uint32_t base, int ncol, int kcol, int lane) {
    uint32_t addr = base + tile_off(ncol + (lane & 7), (kcol >> 3) + ((lane >> 3) & 1));
    asm volatile("ldmatrix.sync.aligned.m8n8.x2.shared.b16 {%0,%1}, [%2];"
        : "=r"(b[0]), "=r"(b[1]) : "r"(addr));
}
__device__ __forceinline__ void mma16816(float* d, const uint32_t* a, const uint32_t* b) {
    asm volatile("mma.sync.aligned.m16n8k16.row.col.f32.f16.f16.f32 "
        "{%0,%1,%2,%3}, {%4,%5,%6,%7}, {%8,%9}, {%0,%1,%2,%3};"
        : "+f"(d[0]), "+f"(d[1]), "+f"(d[2]), "+f"(d[3])
        : "r"(a[0]), "r"(a[1]), "r"(a[2]), "r"(a[3]), "r"(b[0]), "r"(b[1]));
}
__device__ __forceinline__ float leaky_f(float v) { return v < 0.f ? 0.2f * v : v; }

__device__ __forceinline__ void mma_core16(uint32_t sA, uint32_t sB, int wm, int wn, int lane,
                                           float acc[2][4][4]) {
#pragma unroll 1
    for (int ks = 0; ks < 8; ks++) {
        const int kc = ks * 16;
        uint32_t ah[2][4], al[2][4], bh[4][2], bl[4][2];
#pragma unroll
        for (int mi = 0; mi < 2; mi++) {
            ldmA(ah[mi], sA, wm * 32 + mi * 16, kc, lane);
            ldmA(al[mi], sA + 32768, wm * 32 + mi * 16, kc, lane);
        }
#pragma unroll
        for (int ni = 0; ni < 4; ni++) {
            ldmB(bh[ni], sB, wn * 32 + ni * 8, kc, lane);
            ldmB(bl[ni], sB + 32768, wn * 32 + ni * 8, kc, lane);
        }
#pragma unroll
        for (int mi = 0; mi < 2; mi++)
#pragma unroll
            for (int ni = 0; ni < 4; ni++) {
                mma16816(acc[mi][ni], ah[mi], bh[ni]);
                mma16816(acc[mi][ni], ah[mi], bl[ni]);
                mma16816(acc[mi][ni], al[mi], bh[ni]);
            }
    }
}
#define ACC_ZERO2(acc) do { \
    _Pragma("unroll") for (int mi = 0; mi < 2; mi++) \
    _Pragma("unroll") for (int ni = 0; ni < 4; ni++) \
    _Pragma("unroll") for (int j = 0; j < 4; j++) acc[mi][ni][j] = 0.f; } while (0)

// ---------------- scratch ----------------
__device__ __half g_sh[81920 * 128], g_sl[81920 * 128];
__device__ __half g_w1h[128 * 128],  g_w1l[128 * 128];
__device__ __half g_w2h[1024 * 128], g_w2l[1024 * 128];
__device__ __half g_wlh[512 * 128],  g_wll[512 * 128];
__device__ __half g_wrh[512 * 128],  g_wrl[512 * 128];
__device__ float g_xn[65536];
__device__ __half g_D[268435456];
__device__ __half g_XLR[5 * 16384 * 512];
__device__ float g_gf[5 * 4 * 1024];
__device__ float g_attn[16];
__device__ int   g_nbr[4 * 16384 * 16];
__device__ float g_res[4 * 16384 * 128];

// ---------------- preludes ----------------
__global__ void split_seq_kernel(const float* __restrict__ seq) {
    size_t i = (size_t)blockIdx.x * 256 + threadIdx.x;
    if (i < 5120) ((float4*)g_gf)[i] = make_float4(0.f, 0.f, 0.f, 0.f);
    float4 v = ((const float4*)seq)[i];
    float x[4] = {v.x, v.y, v.z, v.w};
    unsigned short h[4], l[4];
#pragma unroll
    for (int j = 0; j < 4; j++) {
        __half hb = __float2half_rn(x[j]);
        h[j] = __half_as_ushort(hb);
        l[j] = __half_as_ushort(__float2half_rn(x[j] - __half2float(hb)));
    }
    uint2 H, L;
    H.x = ((uint32_t)h[1] << 16) | h[0]; H.y = ((uint32_t)h[3] << 16) | h[2];
    L.x = ((uint32_t)l[1] << 16) | l[0]; L.y = ((uint32_t)l[3] << 16) | l[2];
    ((uint2*)g_sh)[i] = H; ((uint2*)g_sl)[i] = L;
}
__global__ void norm_kernel(const float* __restrict__ seq) {
    int r = blockIdx.x * 128 + threadIdx.x;
    const float4* p = (const float4*)(seq + (size_t)r * 128);
    float s = 0.f;
#pragma unroll 8
    for (int i = 0; i < 32; i++) { float4 v = p[i]; s += v.x*v.x + v.y*v.y + v.z*v.z + v.w*v.w; }
    g_xn[r] = s;
}
__global__ void tsplit_kernel(const float* __restrict__ src, __half* __restrict__ dh,
                              __half* __restrict__ dl, int N) {
    __shared__ float t[32][33];
    int n0 = blockIdx.x * 32, k0 = blockIdx.y * 32;
    int tx = threadIdx.x, ty = threadIdx.y;
#pragma unroll
    for (int j = 0; j < 4; j++) t[ty + 8 * j][tx] = src[(size_t)(k0 + ty + 8 * j) * N + n0 + tx];
    __syncthreads();
#pragma unroll
    for (int j = 0; j < 4; j++) {
        int n = n0 + ty + 8 * j, k = k0 + tx;
        float v = t[tx][ty + 8 * j];
        __half hb = __float2half_rn(v);
        dh[(size_t)n * 128 + k] = hb;
        dl[(size_t)n * 128 + k] = __float2half_rn(v - __half2float(hb));
    }
}

// ---------------- dist: pure GEMM, scores fp16 to g_D ----------------
#define DSM 99328
__global__ __launch_bounds__(512, 1) void dist_kernel() {
    extern __shared__ char sm[];
    const uint32_t sA = s2u(sm);
    const int tid = threadIdx.x, lane = tid & 31, wid = tid >> 5;
    const int wm = wid & 3, wn = wid >> 2;
    const int qt = blockIdx.x, b = blockIdx.y, fr = blockIdx.z;

    const size_t yoff = ((size_t)4 * NPTS + b * MP + qt * 128) * 128;
    const size_t xbase = ((size_t)fr * NPTS + b * MP) * 128;
    const float* xng = g_xn + fr * NPTS + b * MP;

    fill_tile_async<512>(sA, g_sh + yoff, tid);
    fill_tile_async<512>(sA + 32768, g_sh + xbase, tid);
    if (tid < 32) CP16(sA + 98304 + tid * 16, xng + tid * 4);
    CP_COMMIT(); CP_WAIT0(); __syncthreads();

    __half* dbase = g_D + (size_t)((fr * 4 + b) * 4096 + qt * 128) * 4096;

    for (int cc = 0; cc < 32; cc++) {
        const int cur = cc & 1, nxt = cur ^ 1;
        const uint32_t sBc = sA + 32768 + cur * 32768;
        if (cc + 1 < 32) {
            const uint32_t sBn = sA + 32768 + nxt * 32768;
            fill_tile_async<512>(sBn, g_sh + xbase + (size_t)(cc + 1) * 16384, tid);
            if (tid < 32) CP16(sA + 98304 + nxt * 512 + tid * 16, xng + (cc + 1) * 128 + tid * 4);
        }
        CP_COMMIT();

        float acc[2][4][4];
        ACC_ZERO2(acc);
#pragma unroll 1
        for (int ks = 0; ks < 8; ks++) {
            const int kc = ks * 16;
            uint32_t ah[2][4], bh[4][2];
#pragma unroll
            for (int mi = 0; mi < 2; mi++) ldmA(ah[mi], sA, wm * 32 + mi * 16, kc, lane);
#pragma unroll
            for (int ni = 0; ni < 4; ni++) ldmB(bh[ni], sBc, wn * 32 + ni * 8, kc, lane);
#pragma unroll
            for (int mi = 0; mi < 2; mi++)
#pragma unroll
                for (int ni = 0; ni < 4; ni++) mma16816(acc[mi][ni], ah[mi], bh[ni]);
        }
        const float* xv = (const float*)(sm + 98304 + cur * 512);
        const int r0 = wm * 32 + (lane >> 2);
#pragma unroll
        for (int ni = 0; ni < 4; ni++) {
            const int c0 = wn * 32 + ni * 8 + (lane & 3) * 2;
            float2 x2 = *(const float2*)&xv[c0];
#pragma unroll
            for (int mi = 0; mi < 2; mi++)
#pragma unroll
                for (int jh = 0; jh < 2; jh++) {
                    const int row = r0 + mi * 16 + jh * 8;
                    float s0 = fmaf(-2.f, acc[mi][ni][jh * 2], x2.x);
                    float s1 = fmaf(-2.f, acc[mi][ni][jh * 2 + 1], x2.y);
                    *(__half2*)(dbase + (size_t)row * 4096 + cc * 128 + c0) =
                        __floats2half2_rn(s0, s1);
                }
        }
        CP_WAIT0(); __syncthreads();
    }
}

// ---------------- topk: warp per query over g_D ----------------
__global__ __launch_bounds__(256) void topk_kernel(const float* __restrict__ seq) {
    __shared__ float tsm[8][128];
    __shared__ float cd[8][128];
    __shared__ int   ci[8][128];
    __shared__ int   wcnt[8];
    __shared__ float tauv[8];
    __shared__ int   psm[8][24];
    __shared__ float rsm[8][24];
    const int lane = threadIdx.x & 31, wid = threadIdx.x >> 5;
    const int R = blockIdx.x * 8 + wid;
    const int slice = R >> 12, q = R & 4095;
    const int fr = slice >> 2, b = slice & 3;
    const uint4* dv = (const uint4*)(g_D + (size_t)R * 4096);

    __half2 m0 = __float2half2_rn(65504.f), m1 = m0;
#pragma unroll 4
    for (int i = 0; i < 16; i++) {
        uint4 v = dv[i * 32 + lane];
        m0 = __hmin2(m0, *(__half2*)&v.x); m1 = __hmin2(m1, *(__half2*)&v.y);
        m0 = __hmin2(m0, *(__half2*)&v.z); m1 = __hmin2(m1, *(__half2*)&v.w);
    }
    {
        float2 f0 = __half22float2(m0), f1 = __half22float2(m1);
        tsm[wid][lane * 4 + 0] = f0.x; tsm[wid][lane * 4 + 1] = f0.y;
        tsm[wid][lane * 4 + 2] = f1.x; tsm[wid][lane * 4 + 3] = f1.y;
    }
    if (lane == 0) wcnt[wid] = 0;
    __syncwarp();
    if (lane == 0) {
        float bd[24];
#pragma unroll
        for (int j = 0; j < 24; j++) bd[j] = 3.0e38f;
        for (int i = 0; i < 128; i++) {
            float s = tsm[wid][i];
            if (s < bd[23]) {
                bd[23] = s;
#pragma unroll
                for (int k = 23; k > 0; k--)
                    if (bd[k] < bd[k - 1]) { float tf = bd[k]; bd[k] = bd[k - 1]; bd[k - 1] = tf; }
            }
        }
        tauv[wid] = bd[23];
    }
    __syncwarp();
    const float tau = tauv[wid];

#pragma unroll 2
    for (int i = 0; i < 16; i++) {
        uint4 v = dv[i * 32 + lane];
        const int cb = (i * 32 + lane) * 8;
        uint32_t w[4] = {v.x, v.y, v.z, v.w};
#pragma unroll
        for (int k = 0; k < 4; k++) {
            float2 f = __half22float2(*(__half2*)&w[k]);
            if (f.x <= tau) { int sl = atomicAdd(&wcnt[wid], 1); if (sl < 128) { cd[wid][sl] = f.x; ci[wid][sl] = cb + k * 2; } }
            if (f.y <= tau) { int sl = atomicAdd(&wcnt[wid], 1); if (sl < 128) { cd[wid][sl] = f.y; ci[wid][sl] = cb + k * 2 + 1; } }
        }
    }
    __syncwarp();
    if (lane == 0) {
        float bd[24]; int bi[24];
#pragma unroll
        for (int j = 0; j < 24; j++) { bd[j] = 3.0e38f; bi[j] = 0x7fffffff; }
        int n = wcnt[wid]; if (n > 128) n = 128;
        for (int i = 0; i < n; i++) {
            float s = cd[wid][i]; int cidx = ci[wid][i];
            if (s < bd[23] || (s == bd[23] && cidx < bi[23])) {
                bd[23] = s; bi[23] = cidx;
#pragma unroll
                for (int k = 23; k > 0; k--)
                    if (bd[k] < bd[k - 1] || (bd[k] == bd[k - 1] && bi[k] < bi[k - 1])) {
                        float tf = bd[k]; bd[k] = bd[k - 1]; bd[k - 1] = tf;
                        int tx = bi[k]; bi[k] = bi[k - 1]; bi[k - 1] = tx;
                    }
            }
        }
#pragma unroll
        for (int j = 0; j < 24; j++) psm[wid][j] = bi[j];
    }
    __syncwarp();

    const size_t qoff = ((size_t)4 * NPTS + b * MP + q) * 128;
    const size_t xrow = ((size_t)fr * NPTS + b * MP) * 128;
    const float* xnf = g_xn + fr * NPTS + b * MP;
    float4 qv = ((const float4*)(seq + qoff))[lane];
#pragma unroll 2
    for (int j = 0; j < 24; j++) {
        int c = psm[wid][j];
        float4 cv = ((const float4*)(seq + xrow + (size_t)c * 128))[lane];
        float p = qv.x * cv.x + qv.y * cv.y + qv.z * cv.z + qv.w * cv.w;
#pragma unroll
        for (int o = 16; o; o >>= 1) p += __shfl_xor_sync(0xffffffffu, p, o);
        if (lane == 0) rsm[wid][j] = xnf[c] - 2.f * p;
    }
    __syncwarp();
    if (lane == 0) {
        float bd[16]; int bi[16];
#pragma unroll
        for (int j = 0; j < 16; j++) { bd[j] = 3.0e38f; bi[j] = 0x7fffffff; }
        for (int j = 0; j < 24; j++) {
            float s = rsm[wid][j]; int cidx = psm[wid][j];
            if (s < bd[15] || (s == bd[15] && cidx < bi[15])) {
                bd[15] = s; bi[15] = cidx;
#pragma unroll
                for (int k = 15; k > 0; k--)
                    if (bd[k] < bd[k - 1] || (bd[k] == bd[k - 1] && bi[k] < bi[k - 1])) {
                        float tf = bd[k]; bd[k] = bd[k - 1]; bd[k - 1] = tf;
                        int tx = bi[k]; bi[k] = bi[k - 1]; bi[k - 1] = tx;
                    }
            }
        }
        const size_t nrow = ((size_t)fr * NPTS + b * MP + q) * KNB;
#pragma unroll
        for (int j = 0; j < 16; j++) g_nbr[nrow + j] = b * MP + bi[j];
    }
}

// ---------------- fused H1 + gf (unchanged) ----------------
#define GFSM 196608
__global__ __launch_bounds__(512, 1) void gf_kernel(const float* __restrict__ b1,
                                                    const float* __restrict__ b2) {
    extern __shared__ char sm[];
    const uint32_t sA = s2u(sm), sB0 = sA + 65536, sB1 = sA + 131072;
    const int tid = threadIdx.x, lane = tid & 31, wid = tid >> 5;
    const int wm = wid & 3, wn = wid >> 2;
    const size_t row0 = (size_t)blockIdx.x * 128;

    fill_tile_async<512>(sA, g_sh + row0 * 128, tid);
    fill_tile_async<512>(sA + 32768, g_sl + row0 * 128, tid);
    fill_tile_async<512>(sB0, g_w1h, tid);
    fill_tile_async<512>(sB0 + 32768, g_w1l, tid);
    CP_COMMIT(); CP_WAIT0(); __syncthreads();

    float acc[2][4][4];
    ACC_ZERO2(acc);
    mma_core16(sA, sB0, wm, wn, lane, acc);
    __syncthreads();

    fill_tile_async<512>(sB0, g_w2h, tid); fill_tile_async<512>(sB0 + 32768, g_w2l, tid); CP_COMMIT();
    fill_tile_async<512>(sB1, g_w2h + 16384, tid); fill_tile_async<512>(sB1 + 32768, g_w2l + 16384, tid); CP_COMMIT();

#pragma unroll
    for (int mi = 0; mi < 2; mi++)
#pragma unroll
        for (int ni = 0; ni < 4; ni++) {
            int r = wm * 32 + mi * 16 + (lane >> 2);
            int c = wn * 32 + ni * 8 + (lane & 3) * 2;
            float2 bv = *(const float2*)(b1 + c);
#pragma unroll
            for (int half = 0; half < 2; half++) {
                int rr = r + half * 8;
                float v0 = leaky_f(acc[mi][ni][half * 2]     + bv.x);
                float v1 = leaky_f(acc[mi][ni][half * 2 + 1] + bv.y);
                __half h0 = __float2half_rn(v0), h1 = __float2half_rn(v1);
                __half l0 = __float2half_rn(v0 - __half2float(h0));
                __half l1 = __float2half_rn(v1 - __half2float(h1));
                uint32_t off = tile_off(rr, c >> 3) + (c & 7) * 2;
                *(uint32_t*)(sm + off) =
                    ((uint32_t)__half_as_ushort(h1) << 16) | __half_as_ushort(h0);
                *(uint32_t*)(sm + 32768 + off) =
                    ((uint32_t)__half_as_ushort(l1) << 16) | __half_as_ushort(l0);
            }
        }
    __syncthreads();

    const int t = (int)(row0 >> 14), b = (int)((row0 >> 12) & 3);
    float* gfrow = g_gf + (t * 4 + b) * 1024;
    const float inv = 1.f / 4096.f;

    for (int nb = 0; nb < 8; nb++) {
        CP_WAIT1(); __syncthreads();
        ACC_ZERO2(acc);
        mma_core16(sA, (nb & 1) ? sB1 : sB0, wm, wn, lane, acc);
        __syncthreads();
        if (nb + 2 < 8) {
            uint32_t dst = (nb & 1) ? sB1 : sB0;
            fill_tile_async<512>(dst, g_w2h + (nb + 2) * 16384, tid);
            fill_tile_async<512>(dst + 32768, g_w2l + (nb + 2) * 16384, tid);
        }
        CP_COMMIT();
#pragma unroll
        for (int ni = 0; ni < 4; ni++) {
            int c = wn * 32 + ni * 8 + (lane & 3) * 2;
            float2 bv = *(const float2*)(b2 + nb * 128 + c);
            float s0 = 0.f, s1 = 0.f;
#pragma unroll
            for (int mi = 0; mi < 2; mi++) {
                s0 += leaky_f(acc[mi][ni][0] + bv.x) + leaky_f(acc[mi][ni][2] + bv.x);
                s1 += leaky_f(acc[mi][ni][1] + bv.y) + leaky_f(acc[mi][ni][3] + bv.y);
            }
#pragma unroll
            for (int o = 4; o <= 16; o <<= 1) {
                s0 += __shfl_xor_sync(0xffffffffu, s0, o);
                s1 += __shfl_xor_sync(0xffffffffu, s1, o);
            }
            if (lane < 4) {
                atomicAdd(&gfrow[nb * 128 + c], s0 * inv);
                atomicAdd(&gfrow[nb * 128 + c + 1], s1 * inv);
            }
        }
    }
}

// ---------------- XLR (unchanged) ----------------
#define XLSM 196608
__global__ __launch_bounds__(512, 1) void xlr_kernel() {
    extern __shared__ char sm[];
    const uint32_t sA = s2u(sm), sB0 = sA + 65536, sB1 = sA + 131072;
    const int tid = threadIdx.x, lane = tid & 31, wid = tid >> 5;
    const int wm = wid & 3, wn = wid >> 2;
    const int z = blockIdx.y;
    const size_t row0 = (size_t)blockIdx.x * 128;
    const __half* Wh = (z == 4) ? g_wlh : g_wrh;
    const __half* Wl = (z == 4) ? g_wll : g_wrl;

    fill_tile_async<512>(sA, g_sh + ((size_t)z * NPTS + row0) * 128, tid);
    fill_tile_async<512>(sA + 32768, g_sl + ((size_t)z * NPTS + row0) * 128, tid);
    fill_tile_async<512>(sB0, Wh, tid); fill_tile_async<512>(sB0 + 32768, Wl, tid); CP_COMMIT();
    fill_tile_async<512>(sB1, Wh + 16384, tid); fill_tile_async<512>(sB1 + 32768, Wl + 16384, tid); CP_COMMIT();

    __half* dstb = g_XLR + ((size_t)z * NPTS + row0) * 512;
    for (int nb = 0; nb < 4; nb++) {
        CP_WAIT1(); __syncthreads();
        float acc[2][4][4];
        ACC_ZERO2(acc);
        mma_core16(sA, (nb & 1) ? sB1 : sB0, wm, wn, lane, acc);
        __syncthreads();
        if (nb + 2 < 4) {
            uint32_t dst = (nb & 1) ? sB1 : sB0;
            fill_tile_async<512>(dst, Wh + (nb + 2) * 16384, tid);
            fill_tile_async<512>(dst + 32768, Wl + (nb + 2) * 16384, tid);
        }
        CP_COMMIT();
#pragma unroll
        for (int mi = 0; mi < 2; mi++)
#pragma unroll
            for (int ni = 0; ni < 4; ni++) {
                int r = wm * 32 + mi * 16 + (lane >> 2);
                int c = wn * 32 + ni * 8 + (lane & 3) * 2;
                *(__half2*)(dstb + (size_t)r * 512 + nb * 128 + c) =
                    __floats2half2_rn(acc[mi][ni][0], acc[mi][ni][1]);
                *(__half2*)(dstb + (size_t)(r + 8) * 512 + nb * 128 + c) =
                    __floats2half2_rn(acc[mi][ni][2], acc[mi][ni][3]);
            }
    }
}

// ---------------- attn ----------------
__global__ void attn_kernel() {
    __shared__ float sc[16];
    const int tid = threadIdx.x, w = tid >> 5, lane = tid & 31;
    const int b = w >> 2, t = w & 3;
    float acc = 0.f;
    for (int g = lane; g < 1024; g += 32)
        acc += g_gf[(16 + b) * 1024 + g] * g_gf[(t * 4 + b) * 1024 + g];
#pragma unroll
    for (int o = 16; o; o >>= 1) acc += __shfl_xor_sync(0xffffffffu, acc, o);
    if (lane == 0) sc[b * 4 + t] = acc * (1.f / 32.f);
    __syncthreads();
    if (tid < 4) {
        int bb = tid;
        float m = sc[bb * 4];
        for (int i = 1; i < 4; i++) m = fmaxf(m, sc[bb * 4 + i]);
        float e[4], s = 0.f;
        for (int i = 0; i < 4; i++) { e[i] = expf(sc[bb * 4 + i] - m); s += e[i]; }
        for (int i = 0; i < 4; i++) g_attn[bb * 4 + i] = e[i] / s;
    }
}

// ---------------- GAT: fp32 smem with 516 pad (conflict-free) ----------------
__global__ __launch_bounds__(128) void gat_kernel(const float* __restrict__ att_w) {
    __shared__ float xls[16 * 516];   // fp32, padded rows: bank varies with k
    __shared__ float xrs[512], aws[512], es[64], as_[64];
    __shared__ int nb[16];
    const int tid = threadIdx.x, n = blockIdx.x, fr = blockIdx.y;
    const __half* XL = g_XLR + (size_t)4 * NPTS * 512;
    const __half* XR = g_XLR + (size_t)fr * NPTS * 512;
    {
        __half2 a = ((const __half2*)(XR + (size_t)n * 512))[tid * 2];
        __half2 b2_ = ((const __half2*)(XR + (size_t)n * 512))[tid * 2 + 1];
        float2 fa = __half22float2(a), fb = __half22float2(b2_);
        xrs[tid * 4] = fa.x; xrs[tid * 4 + 1] = fa.y;
        xrs[tid * 4 + 2] = fb.x; xrs[tid * 4 + 3] = fb.y;
    }
    *(float4*)&aws[tid * 4] = *(const float4*)(att_w + tid * 4);
    if (tid < 16) nb[tid] = g_nbr[((size_t)fr * NPTS + n) * KNB + tid];
    __syncthreads();
#pragma unroll
    for (int k = 0; k < 16; k++) {    // gather fp16 -> fp32 smem (converted once)
        uint2 u = ((const uint2*)(XL + (size_t)nb[k] * 512))[tid];
        float2 f0 = __half22float2(*(__half2*)&u.x);
        float2 f1 = __half22float2(*(__half2*)&u.y);
        float* dst = &xls[k * 516 + tid * 4];
        dst[0] = f0.x; dst[1] = f0.y; dst[2] = f1.x; dst[3] = f1.y;
    }
    __syncthreads();
    {
        const int pr = tid >> 1, hf = tid & 1;
        const int k = pr & 15, h = pr >> 4;
        const float* xk = &xls[k * 516 + h * 128];
        const float* xr = &xrs[h * 128];
        const float* aw = &aws[h * 128];
        float acc = 0.f;
#pragma unroll 4
        for (int c0 = 0; c0 < 64; c0++) {
            int c = hf * 64 + ((c0 + pr + hf * 16) & 63);
            float v = xk[c] + xr[c];
            acc += aw[c] * (v < 0.f ? 0.2f * v : v);
        }
        acc += __shfl_xor_sync(0xffffffffu, acc, 1);
        if (!hf) es[h * 16 + k] = acc;
    }
    __syncthreads();
    if (tid < 4) {
        const int h = tid;
        float m = -1e30f;
        for (int k = 0; k < 16; k++) m = fmaxf(m, es[h * 16 + k]);
        float ex[16], s = 0.f;
        for (int k = 0; k < 16; k++) { ex[k] = expf(es[h * 16 + k] - m); s += ex[k]; }
        for (int k = 0; k < 16; k++) as_[h * 16 + k] = ex[k] / s;
    }
    __syncthreads();
    float o = 0.f;
#pragma unroll
    for (int h = 0; h < 4; h++) {
        float oh = 0.f;
#pragma unroll
        for (int k = 0; k < 16; k++)
            oh += as_[h * 16 + k] * xls[k * 516 + h * 128 + tid];
        o += oh;
    }
    g_res[((size_t)fr * NPTS + n) * 128 + tid] = o * 0.25f;
}
__global__ __launch_bounds__(128) void final_kernel(const float* __restrict__ seq, float* __restrict__ out) {
    const int n = blockIdx.x, c = threadIdx.x, b = n >> 12;
    float w = 0.f;
#pragma unroll
    for (int i = 0; i < 4; i++)
        w += g_attn[b * 4 + i] * g_res[((size_t)i * NPTS + n) * 128 + c];
    const float* last = seq + (size_t)4 * NPTS * 128;
    out[(size_t)n * 256 + c] = last[(size_t)n * 128 + c];
    out[(size_t)n * 256 + 128 + c] = w;
}

// ---------------- launch: topk at my #4 (ncu target this round) ----------------
extern "C" void kernel_launch(void* const* d_in, const int* in_sizes, int n_in,
                              void* d_out, int out_size) {
    (void)in_sizes; (void)n_in; (void)out_size;
    const float* seq = (const float*)d_in[0];
    const float* W1  = (const float*)d_in[1];
    const float* b1  = (const float*)d_in[2];
    const float* W2  = (const float*)d_in[3];
    const float* b2  = (const float*)d_in[4];
    const float* Wl  = (const float*)d_in[5];
    const float* Wr  = (const float*)d_in[6];
    const float* aw  = (const float*)d_in[7];
    float* out = (float*)d_out;

    __half *pw1h, *pw1l, *pw2h, *pw2l, *pwlh, *pwll, *pwrh, *pwrl;
    cudaGetSymbolAddress((void**)&pw1h, g_w1h); cudaGetSymbolAddress((void**)&pw1l, g_w1l);
    cudaGetSymbolAddress((void**)&pw2h, g_w2h); cudaGetSymbolAddress((void**)&pw2l, g_w2l);
    cudaGetSymbolAddress((void**)&pwlh, g_wlh); cudaGetSymbolAddress((void**)&pwll, g_wll);
    cudaGetSymbolAddress((void**)&pwrh, g_wrh); cudaGetSymbolAddress((void**)&pwrl, g_wrl);

    cudaFuncSetAttribute(gf_kernel,   cudaFuncAttributeMaxDynamicSharedMemorySize, GFSM);
    cudaFuncSetAttribute(xlr_kernel,  cudaFuncAttributeMaxDynamicSharedMemorySize, XLSM);
    cudaFuncSetAttribute(dist_kernel, cudaFuncAttributeMaxDynamicSharedMemorySize, DSM);

    split_seq_kernel<<<10240, 256>>>(seq);                       // 1 (incl. gf zero)
    norm_kernel<<<512, 128>>>(seq);                              // 2
    dist_kernel<<<dim3(32, 4, 4), 512, DSM>>>();                 // 3
    topk_kernel<<<8192, 256>>>(seq);                             // 4 <- ncu target
    tsplit_kernel<<<dim3(4, 4),  dim3(32, 8)>>>(W1, pw1h, pw1l, 128);
    tsplit_kernel<<<dim3(32, 4), dim3(32, 8)>>>(W2, pw2h, pw2l, 1024);
    tsplit_kernel<<<dim3(16, 4), dim3(32, 8)>>>(Wl, pwlh, pwll, 512);
    tsplit_kernel<<<dim3(16, 4), dim3(32, 8)>>>(Wr, pwrh, pwrl, 512);
    gf_kernel<<<640, 512, GFSM>>>(b1, b2);
    attn_kernel<<<1, 512>>>();
    xlr_kernel<<<dim3(128, 5), 512, XLSM>>>();
    gat_kernel<<<dim3(NPTS, 4), 128>>>(aw);
    final_kernel<<<NPTS, 128>>>(seq, out);
}

// round 16
// speedup vs baseline: 1.9462x; 1.9462x over previous
#include <cuda_runtime.h>
#include <cuda_fp16.h>
#include <cstdint>

#define NPTS 16384
#define MP   4096
#define KNB  16

// ---------------- helpers ----------------
__device__ __forceinline__ uint32_t s2u(const void* p) {
    uint32_t a;
    asm("{ .reg .u64 t; cvta.to.shared.u64 t, %1; cvt.u32.u64 %0, t; }" : "=r"(a) : "l"(p));
    return a;
}
#define CP16(dst, src) asm volatile("cp.async.cg.shared.global [%0], [%1], 16;" :: "r"(dst), "l"(src))
#define CP_COMMIT()    asm volatile("cp.async.commit_group;" ::: "memory")
#define CP_WAIT0()     asm volatile("cp.async.wait_group 0;" ::: "memory")
#define CP_WAIT1()     asm volatile("cp.async.wait_group 1;" ::: "memory")

__device__ __forceinline__ uint32_t tile_off(int r, int c16) {
    return (uint32_t)(r * 256 + ((c16 ^ (r & 7)) << 4));
}
template <int NT>
__device__ __forceinline__ void fill_tile_async(uint32_t dst, const __half* __restrict__ src, int tid) {
#pragma unroll
    for (int it = 0; it < 2048 / NT; it++) {
        int idx = tid + it * NT;
        int r = idx >> 4, c16 = idx & 15;
        CP16(dst + tile_off(r, c16), src + r * 128 + c16 * 8);
    }
}
__device__ __forceinline__ void ldmA(uint32_t* a, uint32_t base, int mrow, int kcol, int lane) {
    uint32_t addr = base + tile_off(mrow + (lane & 15), (kcol >> 3) + (lane >> 4));
    asm volatile("ldmatrix.sync.aligned.m8n8.x4.shared.b16 {%0,%1,%2,%3}, [%4];"
        : "=r"(a[0]), "=r"(a[1]), "=r"(a[2]), "=r"(a[3]) : "r"(addr));
}
__device__ __forceinline__ void ldmB(uint32_t* b, uint32_t base, int ncol, int kcol, int lane) {
    uint32_t addr = base + tile_off(ncol + (lane & 7), (kcol >> 3) + ((lane >> 3) & 1));
    asm volatile("ldmatrix.sync.aligned.m8n8.x2.shared.b16 {%0,%1}, [%2];"
        : "=r"(b[0]), "=r"(b[1]) : "r"(addr));
}
__device__ __forceinline__ void mma16816(float* d, const uint32_t* a, const uint32_t* b) {
    asm volatile("mma.sync.aligned.m16n8k16.row.col.f32.f16.f16.f32 "
        "{%0,%1,%2,%3}, {%4,%5,%6,%7}, {%8,%9}, {%0,%1,%2,%3};"
        : "+f"(d[0]), "+f"(d[1]), "+f"(d[2]), "+f"(d[3])
        : "r"(a[0]), "r"(a[1]), "r"(a[2]), "r"(a[3]), "r"(b[0]), "r"(b[1]));
}
__device__ __forceinline__ float leaky_f(float v) { return v < 0.f ? 0.2f * v : v; }

__device__ __forceinline__ void mma_core16(uint32_t sA, uint32_t sB, int wm, int wn, int lane,
                                           float acc[2][4][4]) {
#pragma unroll 1
    for (int ks = 0; ks < 8; ks++) {
        const int kc = ks * 16;
        uint32_t ah[2][4], al[2][4], bh[4][2], bl[4][2];
#pragma unroll
        for (int mi = 0; mi < 2; mi++) {
            ldmA(ah[mi], sA, wm * 32 + mi * 16, kc, lane);
            ldmA(al[mi], sA + 32768, wm * 32 + mi * 16, kc, lane);
        }
#pragma unroll
        for (int ni = 0; ni < 4; ni++) {
            ldmB(bh[ni], sB, wn * 32 + ni * 8, kc, lane);
            ldmB(bl[ni], sB + 32768, wn * 32 + ni * 8, kc, lane);
        }
#pragma unroll
        for (int mi = 0; mi < 2; mi++)
#pragma unroll
            for (int ni = 0; ni < 4; ni++) {
                mma16816(acc[mi][ni], ah[mi], bh[ni]);
                mma16816(acc[mi][ni], ah[mi], bl[ni]);
                mma16816(acc[mi][ni], al[mi], bh[ni]);
            }
    }
}
#define ACC_ZERO2(acc) do { \
    _Pragma("unroll") for (int mi = 0; mi < 2; mi++) \
    _Pragma("unroll") for (int ni = 0; ni < 4; ni++) \
    _Pragma("unroll") for (int j = 0; j < 4; j++) acc[mi][ni][j] = 0.f; } while (0)

// ---------------- scratch ----------------
__device__ __half g_sh[81920 * 128], g_sl[81920 * 128];
__device__ __half g_w1h[128 * 128],  g_w1l[128 * 128];
__device__ __half g_w2h[1024 * 128], g_w2l[1024 * 128];
__device__ __half g_wlh[512 * 128],  g_wll[512 * 128];
__device__ __half g_wrh[512 * 128],  g_wrl[512 * 128];
__device__ float g_xn[65536];
__device__ __half g_D[268435456];
__device__ __half g_XLR[5 * 16384 * 512];
__device__ float g_gf[5 * 4 * 1024];
__device__ float g_attn[16];
__device__ int   g_nbr[4 * 16384 * 16];
__device__ float g_res[4 * 16384 * 128];

// ---------------- preludes ----------------
__global__ void split_seq_kernel(const float* __restrict__ seq) {
    size_t i = (size_t)blockIdx.x * 256 + threadIdx.x;
    if (i < 5120) ((float4*)g_gf)[i] = make_float4(0.f, 0.f, 0.f, 0.f);
    float4 v = ((const float4*)seq)[i];
    float x[4] = {v.x, v.y, v.z, v.w};
    unsigned short h[4], l[4];
#pragma unroll
    for (int j = 0; j < 4; j++) {
        __half hb = __float2half_rn(x[j]);
        h[j] = __half_as_ushort(hb);
        l[j] = __half_as_ushort(__float2half_rn(x[j] - __half2float(hb)));
    }
    uint2 H, L;
    H.x = ((uint32_t)h[1] << 16) | h[0]; H.y = ((uint32_t)h[3] << 16) | h[2];
    L.x = ((uint32_t)l[1] << 16) | l[0]; L.y = ((uint32_t)l[3] << 16) | l[2];
    ((uint2*)g_sh)[i] = H; ((uint2*)g_sl)[i] = L;
}
__global__ void norm_kernel(const float* __restrict__ seq) {
    int r = blockIdx.x * 128 + threadIdx.x;
    const float4* p = (const float4*)(seq + (size_t)r * 128);
    float s = 0.f;
#pragma unroll 8
    for (int i = 0; i < 32; i++) { float4 v = p[i]; s += v.x*v.x + v.y*v.y + v.z*v.z + v.w*v.w; }
    g_xn[r] = s;
}
__global__ void tsplit_kernel(const float* __restrict__ src, __half* __restrict__ dh,
                              __half* __restrict__ dl, int N) {
    __shared__ float t[32][33];
    int n0 = blockIdx.x * 32, k0 = blockIdx.y * 32;
    int tx = threadIdx.x, ty = threadIdx.y;
#pragma unroll
    for (int j = 0; j < 4; j++) t[ty + 8 * j][tx] = src[(size_t)(k0 + ty + 8 * j) * N + n0 + tx];
    __syncthreads();
#pragma unroll
    for (int j = 0; j < 4; j++) {
        int n = n0 + ty + 8 * j, k = k0 + tx;
        float v = t[tx][ty + 8 * j];
        __half hb = __float2half_rn(v);
        dh[(size_t)n * 128 + k] = hb;
        dl[(size_t)n * 128 + k] = __float2half_rn(v - __half2float(hb));
    }
}

// ---------------- dist: pure GEMM, scores fp16 to g_D ----------------
#define DSM 99328
__global__ __launch_bounds__(512, 1) void dist_kernel() {
    extern __shared__ char sm[];
    const uint32_t sA = s2u(sm);
    const int tid = threadIdx.x, lane = tid & 31, wid = tid >> 5;
    const int wm = wid & 3, wn = wid >> 2;
    const int qt = blockIdx.x, b = blockIdx.y, fr = blockIdx.z;

    const size_t yoff = ((size_t)4 * NPTS + b * MP + qt * 128) * 128;
    const size_t xbase = ((size_t)fr * NPTS + b * MP) * 128;
    const float* xng = g_xn + fr * NPTS + b * MP;

    fill_tile_async<512>(sA, g_sh + yoff, tid);
    fill_tile_async<512>(sA + 32768, g_sh + xbase, tid);
    if (tid < 32) CP16(sA + 98304 + tid * 16, xng + tid * 4);
    CP_COMMIT(); CP_WAIT0(); __syncthreads();

    __half* dbase = g_D + (size_t)((fr * 4 + b) * 4096 + qt * 128) * 4096;

    for (int cc = 0; cc < 32; cc++) {
        const int cur = cc & 1, nxt = cur ^ 1;
        const uint32_t sBc = sA + 32768 + cur * 32768;
        if (cc + 1 < 32) {
            const uint32_t sBn = sA + 32768 + nxt * 32768;
            fill_tile_async<512>(sBn, g_sh + xbase + (size_t)(cc + 1) * 16384, tid);
            if (tid < 32) CP16(sA + 98304 + nxt * 512 + tid * 16, xng + (cc + 1) * 128 + tid * 4);
        }
        CP_COMMIT();

        float acc[2][4][4];
        ACC_ZERO2(acc);
#pragma unroll 1
        for (int ks = 0; ks < 8; ks++) {
            const int kc = ks * 16;
            uint32_t ah[2][4], bh[4][2];
#pragma unroll
            for (int mi = 0; mi < 2; mi++) ldmA(ah[mi], sA, wm * 32 + mi * 16, kc, lane);
#pragma unroll
            for (int ni = 0; ni < 4; ni++) ldmB(bh[ni], sBc, wn * 32 + ni * 8, kc, lane);
#pragma unroll
            for (int mi = 0; mi < 2; mi++)
#pragma unroll
                for (int ni = 0; ni < 4; ni++) mma16816(acc[mi][ni], ah[mi], bh[ni]);
        }
        const float* xv = (const float*)(sm + 98304 + cur * 512);
        const int r0 = wm * 32 + (lane >> 2);
#pragma unroll
        for (int ni = 0; ni < 4; ni++) {
            const int c0 = wn * 32 + ni * 8 + (lane & 3) * 2;
            float2 x2 = *(const float2*)&xv[c0];
#pragma unroll
            for (int mi = 0; mi < 2; mi++)
#pragma unroll
                for (int jh = 0; jh < 2; jh++) {
                    const int row = r0 + mi * 16 + jh * 8;
                    float s0 = fmaf(-2.f, acc[mi][ni][jh * 2], x2.x);
                    float s1 = fmaf(-2.f, acc[mi][ni][jh * 2 + 1], x2.y);
                    *(__half2*)(dbase + (size_t)row * 4096 + cc * 128 + c0) =
                        __floats2half2_rn(s0, s1);
                }
        }
        CP_WAIT0(); __syncthreads();
    }
}

// ---------------- topk: warp-parallel selection (no serial lane-0 loops) ----------------
__global__ __launch_bounds__(256) void topk_kernel(const float* __restrict__ seq) {
    __shared__ float cd[8][128];     // collected fp16 scores -> later refined fp32
    __shared__ int   ci[8][128];     // collected indices
    __shared__ int   wcnt[8];
    const int lane = threadIdx.x & 31, wid = threadIdx.x >> 5;
    const int R = blockIdx.x * 8 + wid;
    const int slice = R >> 12, q = R & 4095;
    const int fr = slice >> 2, b = slice & 3;
    const uint4* dv = (const uint4*)(g_D + (size_t)R * 4096);

    // pass 1: per-lane chain mins (4 fp16 chains) over 4096 scores
    __half2 m0 = __float2half2_rn(65504.f), m1 = m0;
#pragma unroll 4
    for (int i = 0; i < 16; i++) {
        uint4 v = dv[i * 32 + lane];
        m0 = __hmin2(m0, *(__half2*)&v.x); m1 = __hmin2(m1, *(__half2*)&v.y);
        m0 = __hmin2(m0, *(__half2*)&v.z); m1 = __hmin2(m1, *(__half2*)&v.w);
    }
    float vals[4];
    { float2 f0 = __half22float2(m0), f1 = __half22float2(m1);
      vals[0] = f0.x; vals[1] = f0.y; vals[2] = f1.x; vals[3] = f1.y; }
    if (lane == 0) wcnt[wid] = 0;

    // tau = 24th smallest of the 128 chain mins: 24 warp-min extractions (no divergence)
    float tau = 3.0e38f;
#pragma unroll 1
    for (int e = 0; e < 24; e++) {
        float lm = vals[0]; int li = 0;
#pragma unroll
        for (int j = 1; j < 4; j++) if (vals[j] < lm) { lm = vals[j]; li = j; }
        float wmin = lm;
#pragma unroll
        for (int o = 16; o; o >>= 1) wmin = fminf(wmin, __shfl_xor_sync(0xffffffffu, wmin, o));
        unsigned bal = __ballot_sync(0xffffffffu, lm == wmin);
        if (lane == (__ffs(bal) - 1)) vals[li] = 3.0e38f;
        tau = wmin;
    }
    __syncwarp();
    const __half2 tau2 = __float2half2_rn(tau);

    // pass 2: collect passers (tau >= true 24th => n >= 24; deterministic set)
#pragma unroll 1
    for (int i = 0; i < 16; i++) {
        uint4 v = dv[i * 32 + lane];
        const int cb = (i * 32 + lane) * 8;
        uint32_t w[4] = {v.x, v.y, v.z, v.w};
#pragma unroll
        for (int k = 0; k < 4; k++) {
            __half2 h = *(__half2*)&w[k];
            if (!__hbgt2(h, tau2)) {              // at least one half <= tau
                float2 f = __half22float2(h);
                if (f.x <= tau) { int sl = atomicAdd(&wcnt[wid], 1); if (sl < 128) { cd[wid][sl] = f.x; ci[wid][sl] = cb + k * 2; } }
                if (f.y <= tau) { int sl = atomicAdd(&wcnt[wid], 1); if (sl < 128) { cd[wid][sl] = f.y; ci[wid][sl] = cb + k * 2 + 1; } }
            }
        }
    }
    __syncwarp();
    int n = wcnt[wid]; if (n > 128) n = 128;

    // exact fp32 refine of ALL collected candidates (warp-parallel dot per candidate)
    const size_t qoff = ((size_t)4 * NPTS + b * MP + q) * 128;
    const size_t xrow = ((size_t)fr * NPTS + b * MP) * 128;
    const float* xnf = g_xn + fr * NPTS + b * MP;
    float4 qv = ((const float4*)(seq + qoff))[lane];
#pragma unroll 1
    for (int j = 0; j < n; j++) {
        int c = ci[wid][j];
        float4 cv = ((const float4*)(seq + xrow + (size_t)c * 128))[lane];
        float p = qv.x * cv.x + qv.y * cv.y + qv.z * cv.z + qv.w * cv.w;
#pragma unroll
        for (int o = 16; o; o >>= 1) p += __shfl_xor_sync(0xffffffffu, p, o);
        if (lane == 0) cd[wid][j] = xnf[c] - 2.f * p;
    }
    __syncwarp();

    // final: 16 warp-min extractions on packed (ordered-score, idx) u64 keys — exact lex
    unsigned long long key[4];
#pragma unroll
    for (int j = 0; j < 4; j++) {
        int s = lane + 32 * j;
        if (s < n) {
            uint32_t fb = __float_as_uint(cd[wid][s]);
            fb ^= (fb >> 31) ? 0xffffffffu : 0x80000000u;     // order-preserving
            key[j] = ((unsigned long long)fb << 32) | (uint32_t)ci[wid][s];
        } else key[j] = 0xffffffffffffffffull;
    }
    const size_t nrow = ((size_t)fr * NPTS + b * MP + q) * KNB;
#pragma unroll 1
    for (int e = 0; e < 16; e++) {
        unsigned long long lm = key[0]; int li = 0;
#pragma unroll
        for (int j = 1; j < 4; j++) if (key[j] < lm) { lm = key[j]; li = j; }
        unsigned long long wmin = lm;
#pragma unroll
        for (int o = 16; o; o >>= 1) {
            unsigned long long t = __shfl_xor_sync(0xffffffffu, wmin, o);
            if (t < wmin) wmin = t;
        }
        unsigned bal = __ballot_sync(0xffffffffu, lm == wmin);
        if (lane == (__ffs(bal) - 1)) key[li] = 0xffffffffffffffffull;
        if (lane == 0) g_nbr[nrow + e] = b * MP + (int)(uint32_t)(wmin & 0xffffffffu);
    }
}

// ---------------- fused H1 + gf (unchanged) ----------------
#define GFSM 196608
__global__ __launch_bounds__(512, 1) void gf_kernel(const float* __restrict__ b1,
                                                    const float* __restrict__ b2) {
    extern __shared__ char sm[];
    const uint32_t sA = s2u(sm), sB0 = sA + 65536, sB1 = sA + 131072;
    const int tid = threadIdx.x, lane = tid & 31, wid = tid >> 5;
    const int wm = wid & 3, wn = wid >> 2;
    const size_t row0 = (size_t)blockIdx.x * 128;

    fill_tile_async<512>(sA, g_sh + row0 * 128, tid);
    fill_tile_async<512>(sA + 32768, g_sl + row0 * 128, tid);
    fill_tile_async<512>(sB0, g_w1h, tid);
    fill_tile_async<512>(sB0 + 32768, g_w1l, tid);
    CP_COMMIT(); CP_WAIT0(); __syncthreads();

    float acc[2][4][4];
    ACC_ZERO2(acc);
    mma_core16(sA, sB0, wm, wn, lane, acc);
    __syncthreads();

    fill_tile_async<512>(sB0, g_w2h, tid); fill_tile_async<512>(sB0 + 32768, g_w2l, tid); CP_COMMIT();
    fill_tile_async<512>(sB1, g_w2h + 16384, tid); fill_tile_async<512>(sB1 + 32768, g_w2l + 16384, tid); CP_COMMIT();

#pragma unroll
    for (int mi = 0; mi < 2; mi++)
#pragma unroll
        for (int ni = 0; ni < 4; ni++) {
            int r = wm * 32 + mi * 16 + (lane >> 2);
            int c = wn * 32 + ni * 8 + (lane & 3) * 2;
            float2 bv = *(const float2*)(b1 + c);
#pragma unroll
            for (int half = 0; half < 2; half++) {
                int rr = r + half * 8;
                float v0 = leaky_f(acc[mi][ni][half * 2]     + bv.x);
                float v1 = leaky_f(acc[mi][ni][half * 2 + 1] + bv.y);
                __half h0 = __float2half_rn(v0), h1 = __float2half_rn(v1);
                __half l0 = __float2half_rn(v0 - __half2float(h0));
                __half l1 = __float2half_rn(v1 - __half2float(h1));
                uint32_t off = tile_off(rr, c >> 3) + (c & 7) * 2;
                *(uint32_t*)(sm + off) =
                    ((uint32_t)__half_as_ushort(h1) << 16) | __half_as_ushort(h0);
                *(uint32_t*)(sm + 32768 + off) =
                    ((uint32_t)__half_as_ushort(l1) << 16) | __half_as_ushort(l0);
            }
        }
    __syncthreads();

    const int t = (int)(row0 >> 14), b = (int)((row0 >> 12) & 3);
    float* gfrow = g_gf + (t * 4 + b) * 1024;
    const float inv = 1.f / 4096.f;

    for (int nb = 0; nb < 8; nb++) {
        CP_WAIT1(); __syncthreads();
        ACC_ZERO2(acc);
        mma_core16(sA, (nb & 1) ? sB1 : sB0, wm, wn, lane, acc);
        __syncthreads();
        if (nb + 2 < 8) {
            uint32_t dst = (nb & 1) ? sB1 : sB0;
            fill_tile_async<512>(dst, g_w2h + (nb + 2) * 16384, tid);
            fill_tile_async<512>(dst + 32768, g_w2l + (nb + 2) * 16384, tid);
        }
        CP_COMMIT();
#pragma unroll
        for (int ni = 0; ni < 4; ni++) {
            int c = wn * 32 + ni * 8 + (lane & 3) * 2;
            float2 bv = *(const float2*)(b2 + nb * 128 + c);
            float s0 = 0.f, s1 = 0.f;
#pragma unroll
            for (int mi = 0; mi < 2; mi++) {
                s0 += leaky_f(acc[mi][ni][0] + bv.x) + leaky_f(acc[mi][ni][2] + bv.x);
                s1 += leaky_f(acc[mi][ni][1] + bv.y) + leaky_f(acc[mi][ni][3] + bv.y);
            }
#pragma unroll
            for (int o = 4; o <= 16; o <<= 1) {
                s0 += __shfl_xor_sync(0xffffffffu, s0, o);
                s1 += __shfl_xor_sync(0xffffffffu, s1, o);
            }
            if (lane < 4) {
                atomicAdd(&gfrow[nb * 128 + c], s0 * inv);
                atomicAdd(&gfrow[nb * 128 + c + 1], s1 * inv);
            }
        }
    }
}

// ---------------- XLR (unchanged) ----------------
#define XLSM 196608
__global__ __launch_bounds__(512, 1) void xlr_kernel() {
    extern __shared__ char sm[];
    const uint32_t sA = s2u(sm), sB0 = sA + 65536, sB1 = sA + 131072;
    const int tid = threadIdx.x, lane = tid & 31, wid = tid >> 5;
    const int wm = wid & 3, wn = wid >> 2;
    const int z = blockIdx.y;
    const size_t row0 = (size_t)blockIdx.x * 128;
    const __half* Wh = (z == 4) ? g_wlh : g_wrh;
    const __half* Wl = (z == 4) ? g_wll : g_wrl;

    fill_tile_async<512>(sA, g_sh + ((size_t)z * NPTS + row0) * 128, tid);
    fill_tile_async<512>(sA + 32768, g_sl + ((size_t)z * NPTS + row0) * 128, tid);
    fill_tile_async<512>(sB0, Wh, tid); fill_tile_async<512>(sB0 + 32768, Wl, tid); CP_COMMIT();
    fill_tile_async<512>(sB1, Wh + 16384, tid); fill_tile_async<512>(sB1 + 32768, Wl + 16384, tid); CP_COMMIT();

    __half* dstb = g_XLR + ((size_t)z * NPTS + row0) * 512;
    for (int nb = 0; nb < 4; nb++) {
        CP_WAIT1(); __syncthreads();
        float acc[2][4][4];
        ACC_ZERO2(acc);
        mma_core16(sA, (nb & 1) ? sB1 : sB0, wm, wn, lane, acc);
        __syncthreads();
        if (nb + 2 < 4) {
            uint32_t dst = (nb & 1) ? sB1 : sB0;
            fill_tile_async<512>(dst, Wh + (nb + 2) * 16384, tid);
            fill_tile_async<512>(dst + 32768, Wl + (nb + 2) * 16384, tid);
        }
        CP_COMMIT();
#pragma unroll
        for (int mi = 0; mi < 2; mi++)
#pragma unroll
            for (int ni = 0; ni < 4; ni++) {
                int r = wm * 32 + mi * 16 + (lane >> 2);
                int c = wn * 32 + ni * 8 + (lane & 3) * 2;
                *(__half2*)(dstb + (size_t)r * 512 + nb * 128 + c) =
                    __floats2half2_rn(acc[mi][ni][0], acc[mi][ni][1]);
                *(__half2*)(dstb + (size_t)(r + 8) * 512 + nb * 128 + c) =
                    __floats2half2_rn(acc[mi][ni][2], acc[mi][ni][3]);
            }
    }
}

// ---------------- attn ----------------
__global__ void attn_kernel() {
    __shared__ float sc[16];
    const int tid = threadIdx.x, w = tid >> 5, lane = tid & 31;
    const int b = w >> 2, t = w & 3;
    float acc = 0.f;
    for (int g = lane; g < 1024; g += 32)
        acc += g_gf[(16 + b) * 1024 + g] * g_gf[(t * 4 + b) * 1024 + g];
#pragma unroll
    for (int o = 16; o; o >>= 1) acc += __shfl_xor_sync(0xffffffffu, acc, o);
    if (lane == 0) sc[b * 4 + t] = acc * (1.f / 32.f);
    __syncthreads();
    if (tid < 4) {
        int bb = tid;
        float m = sc[bb * 4];
        for (int i = 1; i < 4; i++) m = fmaxf(m, sc[bb * 4 + i]);
        float e[4], s = 0.f;
        for (int i = 0; i < 4; i++) { e[i] = expf(sc[bb * 4 + i] - m); s += e[i]; }
        for (int i = 0; i < 4; i++) g_attn[bb * 4 + i] = e[i] / s;
    }
}

// ---------------- GAT (R14 fp16 version — higher occupancy) ----------------
__global__ __launch_bounds__(128) void gat_kernel(const float* __restrict__ att_w) {
    __shared__ __half xlsh[16 * 512];
    __shared__ float xrs[512], aws[512], es[64], as_[64];
    __shared__ int nb[16];
    const int tid = threadIdx.x, n = blockIdx.x, fr = blockIdx.y;
    const __half* XL = g_XLR + (size_t)4 * NPTS * 512;
    const __half* XR = g_XLR + (size_t)fr * NPTS * 512;
    {
        __half2 a = ((const __half2*)(XR + (size_t)n * 512))[tid * 2];
        __half2 b2_ = ((const __half2*)(XR + (size_t)n * 512))[tid * 2 + 1];
        float2 fa = __half22float2(a), fb = __half22float2(b2_);
        xrs[tid * 4] = fa.x; xrs[tid * 4 + 1] = fa.y;
        xrs[tid * 4 + 2] = fb.x; xrs[tid * 4 + 3] = fb.y;
    }
    *(float4*)&aws[tid * 4] = *(const float4*)(att_w + tid * 4);
    if (tid < 16) nb[tid] = g_nbr[((size_t)fr * NPTS + n) * KNB + tid];
    __syncthreads();
#pragma unroll
    for (int k = 0; k < 16; k++)
        ((uint2*)&xlsh[k * 512])[tid] = ((const uint2*)(XL + (size_t)nb[k] * 512))[tid];
    __syncthreads();
    {
        const int pr = tid >> 1, hf = tid & 1;
        const int k = pr & 15, h = pr >> 4;
        float acc = 0.f;
#pragma unroll 4
        for (int c0 = 0; c0 < 64; c0++) {
            int c = hf * 64 + ((c0 + pr + hf * 16) & 63);
            float v = __half2float(xlsh[k * 512 + h * 128 + c]) + xrs[h * 128 + c];
            acc += aws[h * 128 + c] * (v < 0.f ? 0.2f * v : v);
        }
        acc += __shfl_xor_sync(0xffffffffu, acc, 1);
        if (!hf) es[h * 16 + k] = acc;
    }
    __syncthreads();
    if (tid < 4) {
        const int h = tid;
        float m = -1e30f;
        for (int k = 0; k < 16; k++) m = fmaxf(m, es[h * 16 + k]);
        float ex[16], s = 0.f;
        for (int k = 0; k < 16; k++) { ex[k] = expf(es[h * 16 + k] - m); s += ex[k]; }
        for (int k = 0; k < 16; k++) as_[h * 16 + k] = ex[k] / s;
    }
    __syncthreads();
    float o = 0.f;
#pragma unroll
    for (int h = 0; h < 4; h++) {
        float oh = 0.f;
#pragma unroll
        for (int k = 0; k < 16; k++)
            oh += as_[h * 16 + k] * __half2float(xlsh[k * 512 + h * 128 + tid]);
        o += oh;
    }
    g_res[((size_t)fr * NPTS + n) * 128 + tid] = o * 0.25f;
}
__global__ __launch_bounds__(128) void final_kernel(const float* __restrict__ seq, float* __restrict__ out) {
    const int n = blockIdx.x, c = threadIdx.x, b = n >> 12;
    float w = 0.f;
#pragma unroll
    for (int i = 0; i < 4; i++)
        w += g_attn[b * 4 + i] * g_res[((size_t)i * NPTS + n) * 128 + c];
    const float* last = seq + (size_t)4 * NPTS * 128;
    out[(size_t)n * 256 + c] = last[(size_t)n * 128 + c];
    out[(size_t)n * 256 + 128 + c] = w;
}

// ---------------- launch: topk at my #4 (ncu target) ----------------
extern "C" void kernel_launch(void* const* d_in, const int* in_sizes, int n_in,
                              void* d_out, int out_size) {
    (void)in_sizes; (void)n_in; (void)out_size;
    const float* seq = (const float*)d_in[0];
    const float* W1  = (const float*)d_in[1];
    const float* b1  = (const float*)d_in[2];
    const float* W2  = (const float*)d_in[3];
    const float* b2  = (const float*)d_in[4];
    const float* Wl  = (const float*)d_in[5];
    const float* Wr  = (const float*)d_in[6];
    const float* aw  = (const float*)d_in[7];
    float* out = (float*)d_out;

    __half *pw1h, *pw1l, *pw2h, *pw2l, *pwlh, *pwll, *pwrh, *pwrl;
    cudaGetSymbolAddress((void**)&pw1h, g_w1h); cudaGetSymbolAddress((void**)&pw1l, g_w1l);
    cudaGetSymbolAddress((void**)&pw2h, g_w2h); cudaGetSymbolAddress((void**)&pw2l, g_w2l);
    cudaGetSymbolAddress((void**)&pwlh, g_wlh); cudaGetSymbolAddress((void**)&pwll, g_wll);
    cudaGetSymbolAddress((void**)&pwrh, g_wrh); cudaGetSymbolAddress((void**)&pwrl, g_wrl);

    cudaFuncSetAttribute(gf_kernel,   cudaFuncAttributeMaxDynamicSharedMemorySize, GFSM);
    cudaFuncSetAttribute(xlr_kernel,  cudaFuncAttributeMaxDynamicSharedMemorySize, XLSM);
    cudaFuncSetAttribute(dist_kernel, cudaFuncAttributeMaxDynamicSharedMemorySize, DSM);

    split_seq_kernel<<<10240, 256>>>(seq);                       // 1 (incl. gf zero)
    norm_kernel<<<512, 128>>>(seq);                              // 2
    dist_kernel<<<dim3(32, 4, 4), 512, DSM>>>();                 // 3
    topk_kernel<<<8192, 256>>>(seq);                             // 4 <- ncu target
    tsplit_kernel<<<dim3(4, 4),  dim3(32, 8)>>>(W1, pw1h, pw1l, 128);
    tsplit_kernel<<<dim3(32, 4), dim3(32, 8)>>>(W2, pw2h, pw2l, 1024);
    tsplit_kernel<<<dim3(16, 4), dim3(32, 8)>>>(Wl, pwlh, pwll, 512);
    tsplit_kernel<<<dim3(16, 4), dim3(32, 8)>>>(Wr, pwrh, pwrl, 512);
    gf_kernel<<<640, 512, GFSM>>>(b1, b2);
    attn_kernel<<<1, 512>>>();
    xlr_kernel<<<dim3(128, 5), 512, XLSM>>>();
    gat_kernel<<<dim3(NPTS, 4), 128>>>(aw);
    final_kernel<<<NPTS, 128>>>(seq, out);
}

// round 17
// speedup vs baseline: 2.0745x; 1.0659x over previous
#include <cuda_runtime.h>
#include <cuda_fp16.h>
#include <cstdint>

#define NPTS 16384
#define MP   4096
#define KNB  16

// ---------------- helpers ----------------
__device__ __forceinline__ uint32_t s2u(const void* p) {
    uint32_t a;
    asm("{ .reg .u64 t; cvta.to.shared.u64 t, %1; cvt.u32.u64 %0, t; }" : "=r"(a) : "l"(p));
    return a;
}
#define CP16(dst, src) asm volatile("cp.async.cg.shared.global [%0], [%1], 16;" :: "r"(dst), "l"(src))
#define CP_COMMIT()    asm volatile("cp.async.commit_group;" ::: "memory")
#define CP_WAIT0()     asm volatile("cp.async.wait_group 0;" ::: "memory")
#define CP_WAIT1()     asm volatile("cp.async.wait_group 1;" ::: "memory")

__device__ __forceinline__ uint32_t tile_off(int r, int c16) {
    return (uint32_t)(r * 256 + ((c16 ^ (r & 7)) << 4));
}
template <int NT>
__device__ __forceinline__ void fill_tile_async(uint32_t dst, const __half* __restrict__ src, int tid) {
#pragma unroll
    for (int it = 0; it < 2048 / NT; it++) {
        int idx = tid + it * NT;
        int r = idx >> 4, c16 = idx & 15;
        CP16(dst + tile_off(r, c16), src + r * 128 + c16 * 8);
    }
}
__device__ __forceinline__ void ldmA(uint32_t* a, uint32_t base, int mrow, int kcol, int lane) {
    uint32_t addr = base + tile_off(mrow + (lane & 15), (kcol >> 3) + (lane >> 4));
    asm volatile("ldmatrix.sync.aligned.m8n8.x4.shared.b16 {%0,%1,%2,%3}, [%4];"
        : "=r"(a[0]), "=r"(a[1]), "=r"(a[2]), "=r"(a[3]) : "r"(addr));
}
__device__ __forceinline__ void ldmB(uint32_t* b, uint32_t base, int ncol, int kcol, int lane) {
    uint32_t addr = base + tile_off(ncol + (lane & 7), (kcol >> 3) + ((lane >> 3) & 1));
    asm volatile("ldmatrix.sync.aligned.m8n8.x2.shared.b16 {%0,%1}, [%2];"
        : "=r"(b[0]), "=r"(b[1]) : "r"(addr));
}
__device__ __forceinline__ void mma16816(float* d, const uint32_t* a, const uint32_t* b) {
    asm volatile("mma.sync.aligned.m16n8k16.row.col.f32.f16.f16.f32 "
        "{%0,%1,%2,%3}, {%4,%5,%6,%7}, {%8,%9}, {%0,%1,%2,%3};"
        : "+f"(d[0]), "+f"(d[1]), "+f"(d[2]), "+f"(d[3])
        : "r"(a[0]), "r"(a[1]), "r"(a[2]), "r"(a[3]), "r"(b[0]), "r"(b[1]));
}
__device__ __forceinline__ float leaky_f(float v) { return v < 0.f ? 0.2f * v : v; }

__device__ __forceinline__ void mma_core16(uint32_t sA, uint32_t sB, int wm, int wn, int lane,
                                           float acc[2][4][4]) {
#pragma unroll 1
    for (int ks = 0; ks < 8; ks++) {
        const int kc = ks * 16;
        uint32_t ah[2][4], al[2][4], bh[4][2], bl[4][2];
#pragma unroll
        for (int mi = 0; mi < 2; mi++) {
            ldmA(ah[mi], sA, wm * 32 + mi * 16, kc, lane);
            ldmA(al[mi], sA + 32768, wm * 32 + mi * 16, kc, lane);
        }
#pragma unroll
        for (int ni = 0; ni < 4; ni++) {
            ldmB(bh[ni], sB, wn * 32 + ni * 8, kc, lane);
            ldmB(bl[ni], sB + 32768, wn * 32 + ni * 8, kc, lane);
        }
#pragma unroll
        for (int mi = 0; mi < 2; mi++)
#pragma unroll
            for (int ni = 0; ni < 4; ni++) {
                mma16816(acc[mi][ni], ah[mi], bh[ni]);
                mma16816(acc[mi][ni], ah[mi], bl[ni]);
                mma16816(acc[mi][ni], al[mi], bh[ni]);
            }
    }
}
#define ACC_ZERO2(acc) do { \
    _Pragma("unroll") for (int mi = 0; mi < 2; mi++) \
    _Pragma("unroll") for (int ni = 0; ni < 4; ni++) \
    _Pragma("unroll") for (int j = 0; j < 4; j++) acc[mi][ni][j] = 0.f; } while (0)

// ---------------- scratch ----------------
__device__ __half g_sh[81920 * 128], g_sl[81920 * 128];
__device__ __half g_w1h[128 * 128],  g_w1l[128 * 128];
__device__ __half g_w2h[1024 * 128], g_w2l[1024 * 128];
__device__ __half g_wlh[512 * 128],  g_wll[512 * 128];
__device__ __half g_wrh[512 * 128],  g_wrl[512 * 128];
__device__ float g_xn[65536];
__device__ __half g_D[268435456];   // scores, permuted within each 32-col group
__device__ __half g_XLR[5 * 16384 * 512];
__device__ float g_gf[5 * 4 * 1024];
__device__ float g_attn[16];
__device__ int   g_nbr[4 * 16384 * 16];
__device__ float g_res[4 * 16384 * 128];

// position->candidate unswizzle (swap ni and lane&3 fields in low 5 bits)
__device__ __forceinline__ int unswz(int p) {
    return (p & ~31) | ((p & 6) << 2) | ((p & 24) >> 2) | (p & 1);
}

// ---------------- preludes ----------------
__global__ void split_seq_kernel(const float* __restrict__ seq) {
    size_t i = (size_t)blockIdx.x * 256 + threadIdx.x;
    if (i < 5120) ((float4*)g_gf)[i] = make_float4(0.f, 0.f, 0.f, 0.f);
    float4 v = ((const float4*)seq)[i];
    float x[4] = {v.x, v.y, v.z, v.w};
    unsigned short h[4], l[4];
#pragma unroll
    for (int j = 0; j < 4; j++) {
        __half hb = __float2half_rn(x[j]);
        h[j] = __half_as_ushort(hb);
        l[j] = __half_as_ushort(__float2half_rn(x[j] - __half2float(hb)));
    }
    uint2 H, L;
    H.x = ((uint32_t)h[1] << 16) | h[0]; H.y = ((uint32_t)h[3] << 16) | h[2];
    L.x = ((uint32_t)l[1] << 16) | l[0]; L.y = ((uint32_t)l[3] << 16) | l[2];
    ((uint2*)g_sh)[i] = H; ((uint2*)g_sl)[i] = L;
}
__global__ void norm_kernel(const float* __restrict__ seq) {
    int r = blockIdx.x * 128 + threadIdx.x;
    const float4* p = (const float4*)(seq + (size_t)r * 128);
    float s = 0.f;
#pragma unroll 8
    for (int i = 0; i < 32; i++) { float4 v = p[i]; s += v.x*v.x + v.y*v.y + v.z*v.z + v.w*v.w; }
    g_xn[r] = s;
}
__global__ void tsplit_kernel(const float* __restrict__ src, __half* __restrict__ dh,
                              __half* __restrict__ dl, int N) {
    __shared__ float t[32][33];
    int n0 = blockIdx.x * 32, k0 = blockIdx.y * 32;
    int tx = threadIdx.x, ty = threadIdx.y;
#pragma unroll
    for (int j = 0; j < 4; j++) t[ty + 8 * j][tx] = src[(size_t)(k0 + ty + 8 * j) * N + n0 + tx];
    __syncthreads();
#pragma unroll
    for (int j = 0; j < 4; j++) {
        int n = n0 + ty + 8 * j, k = k0 + tx;
        float v = t[tx][ty + 8 * j];
        __half hb = __float2half_rn(v);
        dh[(size_t)n * 128 + k] = hb;
        dl[(size_t)n * 128 + k] = __float2half_rn(v - __half2float(hb));
    }
}

// ---------------- dist: GEMM, coalesced permuted fp16 stores (STG.128) ----------------
#define DSM 99328
__global__ __launch_bounds__(512, 1) void dist_kernel() {
    extern __shared__ char sm[];
    const uint32_t sA = s2u(sm);
    const int tid = threadIdx.x, lane = tid & 31, wid = tid >> 5;
    const int wm = wid & 3, wn = wid >> 2;
    const int qt = blockIdx.x, b = blockIdx.y, fr = blockIdx.z;

    const size_t yoff = ((size_t)4 * NPTS + b * MP + qt * 128) * 128;
    const size_t xbase = ((size_t)fr * NPTS + b * MP) * 128;
    const float* xng = g_xn + fr * NPTS + b * MP;

    fill_tile_async<512>(sA, g_sh + yoff, tid);
    fill_tile_async<512>(sA + 32768, g_sh + xbase, tid);
    if (tid < 32) CP16(sA + 98304 + tid * 16, xng + tid * 4);
    CP_COMMIT(); CP_WAIT0(); __syncthreads();

    __half* dbase = g_D + (size_t)((fr * 4 + b) * 4096 + qt * 128) * 4096;
    const int pbase = wn * 32 + (lane & 3) * 8;        // permuted in-row position

    for (int cc = 0; cc < 32; cc++) {
        const int cur = cc & 1, nxt = cur ^ 1;
        const uint32_t sBc = sA + 32768 + cur * 32768;
        if (cc + 1 < 32) {
            const uint32_t sBn = sA + 32768 + nxt * 32768;
            fill_tile_async<512>(sBn, g_sh + xbase + (size_t)(cc + 1) * 16384, tid);
            if (tid < 32) CP16(sA + 98304 + nxt * 512 + tid * 16, xng + (cc + 1) * 128 + tid * 4);
        }
        CP_COMMIT();

        float acc[2][4][4];
        ACC_ZERO2(acc);
#pragma unroll 1
        for (int ks = 0; ks < 8; ks++) {
            const int kc = ks * 16;
            uint32_t ah[2][4], bh[4][2];
#pragma unroll
            for (int mi = 0; mi < 2; mi++) ldmA(ah[mi], sA, wm * 32 + mi * 16, kc, lane);
#pragma unroll
            for (int ni = 0; ni < 4; ni++) ldmB(bh[ni], sBc, wn * 32 + ni * 8, kc, lane);
#pragma unroll
            for (int mi = 0; mi < 2; mi++)
#pragma unroll
                for (int ni = 0; ni < 4; ni++) mma16816(acc[mi][ni], ah[mi], bh[ni]);
        }
        const float* xv = (const float*)(sm + 98304 + cur * 512);
        const int r0 = wm * 32 + (lane >> 2);
#pragma unroll
        for (int mi = 0; mi < 2; mi++)
#pragma unroll
            for (int jh = 0; jh < 2; jh++) {
                const int row = r0 + mi * 16 + jh * 8;
                uint32_t pk[4];
#pragma unroll
                for (int ni = 0; ni < 4; ni++) {
                    const int c0 = wn * 32 + ni * 8 + (lane & 3) * 2;
                    float2 x2 = *(const float2*)&xv[c0];
                    __half2 h2 = __floats2half2_rn(fmaf(-2.f, acc[mi][ni][jh * 2], x2.x),
                                                   fmaf(-2.f, acc[mi][ni][jh * 2 + 1], x2.y));
                    pk[ni] = *(uint32_t*)&h2;
                }
                *(uint4*)(dbase + (size_t)row * 4096 + cc * 128 + pbase) =
                    make_uint4(pk[0], pk[1], pk[2], pk[3]);
            }
        CP_WAIT0(); __syncthreads();
    }
}

// ---------------- topk: warp-parallel selection ----------------
__global__ __launch_bounds__(256) void topk_kernel(const float* __restrict__ seq) {
    __shared__ float cd[8][128];
    __shared__ int   ci[8][128];
    __shared__ int   wcnt[8];
    const int lane = threadIdx.x & 31, wid = threadIdx.x >> 5;
    const int R = blockIdx.x * 8 + wid;
    const int slice = R >> 12, q = R & 4095;
    const int fr = slice >> 2, b = slice & 3;
    const uint4* dv = (const uint4*)(g_D + (size_t)R * 4096);

    __half2 m0 = __float2half2_rn(65504.f), m1 = m0;
#pragma unroll 4
    for (int i = 0; i < 16; i++) {
        uint4 v = dv[i * 32 + lane];
        m0 = __hmin2(m0, *(__half2*)&v.x); m1 = __hmin2(m1, *(__half2*)&v.y);
        m0 = __hmin2(m0, *(__half2*)&v.z); m1 = __hmin2(m1, *(__half2*)&v.w);
    }
    float vals[4];
    { float2 f0 = __half22float2(m0), f1 = __half22float2(m1);
      vals[0] = f0.x; vals[1] = f0.y; vals[2] = f1.x; vals[3] = f1.y; }
    if (lane == 0) wcnt[wid] = 0;

    float tau = 3.0e38f;
#pragma unroll 1
    for (int e = 0; e < 24; e++) {
        float lm = vals[0]; int li = 0;
#pragma unroll
        for (int j = 1; j < 4; j++) if (vals[j] < lm) { lm = vals[j]; li = j; }
        float wmin = lm;
#pragma unroll
        for (int o = 16; o; o >>= 1) wmin = fminf(wmin, __shfl_xor_sync(0xffffffffu, wmin, o));
        unsigned bal = __ballot_sync(0xffffffffu, lm == wmin);
        if (lane == (__ffs(bal) - 1)) vals[li] = 3.0e38f;
        tau = wmin;
    }
    __syncwarp();
    const __half2 tau2 = __float2half2_rn(tau);

#pragma unroll 1
    for (int i = 0; i < 16; i++) {
        uint4 v = dv[i * 32 + lane];
        const int cb = (i * 32 + lane) * 8;
        uint32_t w[4] = {v.x, v.y, v.z, v.w};
#pragma unroll
        for (int k = 0; k < 4; k++) {
            __half2 h = *(__half2*)&w[k];
            if (!__hbgt2(h, tau2)) {
                float2 f = __half22float2(h);
                if (f.x <= tau) { int sl = atomicAdd(&wcnt[wid], 1); if (sl < 128) { cd[wid][sl] = f.x; ci[wid][sl] = unswz(cb + k * 2); } }
                if (f.y <= tau) { int sl = atomicAdd(&wcnt[wid], 1); if (sl < 128) { cd[wid][sl] = f.y; ci[wid][sl] = unswz(cb + k * 2 + 1); } }
            }
        }
    }
    __syncwarp();
    int n = wcnt[wid]; if (n > 128) n = 128;

    const size_t qoff = ((size_t)4 * NPTS + b * MP + q) * 128;
    const size_t xrow = ((size_t)fr * NPTS + b * MP) * 128;
    const float* xnf = g_xn + fr * NPTS + b * MP;
    float4 qv = ((const float4*)(seq + qoff))[lane];
#pragma unroll 1
    for (int j = 0; j < n; j++) {
        int c = ci[wid][j];
        float4 cv = ((const float4*)(seq + xrow + (size_t)c * 128))[lane];
        float p = qv.x * cv.x + qv.y * cv.y + qv.z * cv.z + qv.w * cv.w;
#pragma unroll
        for (int o = 16; o; o >>= 1) p += __shfl_xor_sync(0xffffffffu, p, o);
        if (lane == 0) cd[wid][j] = xnf[c] - 2.f * p;
    }
    __syncwarp();

    unsigned long long key[4];
#pragma unroll
    for (int j = 0; j < 4; j++) {
        int s = lane + 32 * j;
        if (s < n) {
            uint32_t fb = __float_as_uint(cd[wid][s]);
            fb ^= (fb >> 31) ? 0xffffffffu : 0x80000000u;
            key[j] = ((unsigned long long)fb << 32) | (uint32_t)ci[wid][s];
        } else key[j] = 0xffffffffffffffffull;
    }
    const size_t nrow = ((size_t)fr * NPTS + b * MP + q) * KNB;
#pragma unroll 1
    for (int e = 0; e < 16; e++) {
        unsigned long long lm = key[0]; int li = 0;
#pragma unroll
        for (int j = 1; j < 4; j++) if (key[j] < lm) { lm = key[j]; li = j; }
        unsigned long long wmin = lm;
#pragma unroll
        for (int o = 16; o; o >>= 1) {
            unsigned long long t = __shfl_xor_sync(0xffffffffu, wmin, o);
            if (t < wmin) wmin = t;
        }
        unsigned bal = __ballot_sync(0xffffffffu, lm == wmin);
        if (lane == (__ffs(bal) - 1)) key[li] = 0xffffffffffffffffull;
        if (lane == 0) g_nbr[nrow + e] = b * MP + (int)(uint32_t)(wmin & 0xffffffffu);
    }
}

// ---------------- fused H1 + gf (unchanged) ----------------
#define GFSM 196608
__global__ __launch_bounds__(512, 1) void gf_kernel(const float* __restrict__ b1,
                                                    const float* __restrict__ b2) {
    extern __shared__ char sm[];
    const uint32_t sA = s2u(sm), sB0 = sA + 65536, sB1 = sA + 131072;
    const int tid = threadIdx.x, lane = tid & 31, wid = tid >> 5;
    const int wm = wid & 3, wn = wid >> 2;
    const size_t row0 = (size_t)blockIdx.x * 128;

    fill_tile_async<512>(sA, g_sh + row0 * 128, tid);
    fill_tile_async<512>(sA + 32768, g_sl + row0 * 128, tid);
    fill_tile_async<512>(sB0, g_w1h, tid);
    fill_tile_async<512>(sB0 + 32768, g_w1l, tid);
    CP_COMMIT(); CP_WAIT0(); __syncthreads();

    float acc[2][4][4];
    ACC_ZERO2(acc);
    mma_core16(sA, sB0, wm, wn, lane, acc);
    __syncthreads();

    fill_tile_async<512>(sB0, g_w2h, tid); fill_tile_async<512>(sB0 + 32768, g_w2l, tid); CP_COMMIT();
    fill_tile_async<512>(sB1, g_w2h + 16384, tid); fill_tile_async<512>(sB1 + 32768, g_w2l + 16384, tid); CP_COMMIT();

#pragma unroll
    for (int mi = 0; mi < 2; mi++)
#pragma unroll
        for (int ni = 0; ni < 4; ni++) {
            int r = wm * 32 + mi * 16 + (lane >> 2);
            int c = wn * 32 + ni * 8 + (lane & 3) * 2;
            float2 bv = *(const float2*)(b1 + c);
#pragma unroll
            for (int half = 0; half < 2; half++) {
                int rr = r + half * 8;
                float v0 = leaky_f(acc[mi][ni][half * 2]     + bv.x);
                float v1 = leaky_f(acc[mi][ni][half * 2 + 1] + bv.y);
                __half h0 = __float2half_rn(v0), h1 = __float2half_rn(v1);
                __half l0 = __float2half_rn(v0 - __half2float(h0));
                __half l1 = __float2half_rn(v1 - __half2float(h1));
                uint32_t off = tile_off(rr, c >> 3) + (c & 7) * 2;
                *(uint32_t*)(sm + off) =
                    ((uint32_t)__half_as_ushort(h1) << 16) | __half_as_ushort(h0);
                *(uint32_t*)(sm + 32768 + off) =
                    ((uint32_t)__half_as_ushort(l1) << 16) | __half_as_ushort(l0);
            }
        }
    __syncthreads();

    const int t = (int)(row0 >> 14), b = (int)((row0 >> 12) & 3);
    float* gfrow = g_gf + (t * 4 + b) * 1024;
    const float inv = 1.f / 4096.f;

    for (int nb = 0; nb < 8; nb++) {
        CP_WAIT1(); __syncthreads();
        ACC_ZERO2(acc);
        mma_core16(sA, (nb & 1) ? sB1 : sB0, wm, wn, lane, acc);
        __syncthreads();
        if (nb + 2 < 8) {
            uint32_t dst = (nb & 1) ? sB1 : sB0;
            fill_tile_async<512>(dst, g_w2h + (nb + 2) * 16384, tid);
            fill_tile_async<512>(dst + 32768, g_w2l + (nb + 2) * 16384, tid);
        }
        CP_COMMIT();
#pragma unroll
        for (int ni = 0; ni < 4; ni++) {
            int c = wn * 32 + ni * 8 + (lane & 3) * 2;
            float2 bv = *(const float2*)(b2 + nb * 128 + c);
            float s0 = 0.f, s1 = 0.f;
#pragma unroll
            for (int mi = 0; mi < 2; mi++) {
                s0 += leaky_f(acc[mi][ni][0] + bv.x) + leaky_f(acc[mi][ni][2] + bv.x);
                s1 += leaky_f(acc[mi][ni][1] + bv.y) + leaky_f(acc[mi][ni][3] + bv.y);
            }
#pragma unroll
            for (int o = 4; o <= 16; o <<= 1) {
                s0 += __shfl_xor_sync(0xffffffffu, s0, o);
                s1 += __shfl_xor_sync(0xffffffffu, s1, o);
            }
            if (lane < 4) {
                atomicAdd(&gfrow[nb * 128 + c], s0 * inv);
                atomicAdd(&gfrow[nb * 128 + c + 1], s1 * inv);
            }
        }
    }
}

// ---------------- XLR (unchanged) ----------------
#define XLSM 196608
__global__ __launch_bounds__(512, 1) void xlr_kernel() {
    extern __shared__ char sm[];
    const uint32_t sA = s2u(sm), sB0 = sA + 65536, sB1 = sA + 131072;
    const int tid = threadIdx.x, lane = tid & 31, wid = tid >> 5;
    const int wm = wid & 3, wn = wid >> 2;
    const int z = blockIdx.y;
    const size_t row0 = (size_t)blockIdx.x * 128;
    const __half* Wh = (z == 4) ? g_wlh : g_wrh;
    const __half* Wl = (z == 4) ? g_wll : g_wrl;

    fill_tile_async<512>(sA, g_sh + ((size_t)z * NPTS + row0) * 128, tid);
    fill_tile_async<512>(sA + 32768, g_sl + ((size_t)z * NPTS + row0) * 128, tid);
    fill_tile_async<512>(sB0, Wh, tid); fill_tile_async<512>(sB0 + 32768, Wl, tid); CP_COMMIT();
    fill_tile_async<512>(sB1, Wh + 16384, tid); fill_tile_async<512>(sB1 + 32768, Wl + 16384, tid); CP_COMMIT();

    __half* dstb = g_XLR + ((size_t)z * NPTS + row0) * 512;
    for (int nb = 0; nb < 4; nb++) {
        CP_WAIT1(); __syncthreads();
        float acc[2][4][4];
        ACC_ZERO2(acc);
        mma_core16(sA, (nb & 1) ? sB1 : sB0, wm, wn, lane, acc);
        __syncthreads();
        if (nb + 2 < 4) {
            uint32_t dst = (nb & 1) ? sB1 : sB0;
            fill_tile_async<512>(dst, Wh + (nb + 2) * 16384, tid);
            fill_tile_async<512>(dst + 32768, Wl + (nb + 2) * 16384, tid);
        }
        CP_COMMIT();
#pragma unroll
        for (int mi = 0; mi < 2; mi++)
#pragma unroll
            for (int ni = 0; ni < 4; ni++) {
                int r = wm * 32 + mi * 16 + (lane >> 2);
                int c = wn * 32 + ni * 8 + (lane & 3) * 2;
                *(__half2*)(dstb + (size_t)r * 512 + nb * 128 + c) =
                    __floats2half2_rn(acc[mi][ni][0], acc[mi][ni][1]);
                *(__half2*)(dstb + (size_t)(r + 8) * 512 + nb * 128 + c) =
                    __floats2half2_rn(acc[mi][ni][2], acc[mi][ni][3]);
            }
    }
}

// ---------------- attn ----------------
__global__ void attn_kernel() {
    __shared__ float sc[16];
    const int tid = threadIdx.x, w = tid >> 5, lane = tid & 31;
    const int b = w >> 2, t = w & 3;
    float acc = 0.f;
    for (int g = lane; g < 1024; g += 32)
        acc += g_gf[(16 + b) * 1024 + g] * g_gf[(t * 4 + b) * 1024 + g];
#pragma unroll
    for (int o = 16; o; o >>= 1) acc += __shfl_xor_sync(0xffffffffu, acc, o);
    if (lane == 0) sc[b * 4 + t] = acc * (1.f / 32.f);
    __syncthreads();
    if (tid < 4) {
        int bb = tid;
        float m = sc[bb * 4];
        for (int i = 1; i < 4; i++) m = fmaxf(m, sc[bb * 4 + i]);
        float e[4], s = 0.f;
        for (int i = 0; i < 4; i++) { e[i] = expf(sc[bb * 4 + i] - m); s += e[i]; }
        for (int i = 0; i < 4; i++) g_attn[bb * 4 + i] = e[i] / s;
    }
}

// ---------------- GAT (fp16 smem) ----------------
__global__ __launch_bounds__(128) void gat_kernel(const float* __restrict__ att_w) {
    __shared__ __half xlsh[16 * 512];
    __shared__ float xrs[512], aws[512], es[64], as_[64];
    __shared__ int nb[16];
    const int tid = threadIdx.x, n = blockIdx.x, fr = blockIdx.y;
    const __half* XL = g_XLR + (size_t)4 * NPTS * 512;
    const __half* XR = g_XLR + (size_t)fr * NPTS * 512;
    {
        __half2 a = ((const __half2*)(XR + (size_t)n * 512))[tid * 2];
        __half2 b2_ = ((const __half2*)(XR + (size_t)n * 512))[tid * 2 + 1];
        float2 fa = __half22float2(a), fb = __half22float2(b2_);
        xrs[tid * 4] = fa.x; xrs[tid * 4 + 1] = fa.y;
        xrs[tid * 4 + 2] = fb.x; xrs[tid * 4 + 3] = fb.y;
    }
    *(float4*)&aws[tid * 4] = *(const float4*)(att_w + tid * 4);
    if (tid < 16) nb[tid] = g_nbr[((size_t)fr * NPTS + n) * KNB + tid];
    __syncthreads();
#pragma unroll
    for (int k = 0; k < 16; k++)
        ((uint2*)&xlsh[k * 512])[tid] = ((const uint2*)(XL + (size_t)nb[k] * 512))[tid];
    __syncthreads();
    {
        const int pr = tid >> 1, hf = tid & 1;
        const int k = pr & 15, h = pr >> 4;
        float acc = 0.f;
#pragma unroll 4
        for (int c0 = 0; c0 < 64; c0++) {
            int c = hf * 64 + ((c0 + pr + hf * 16) & 63);
            float v = __half2float(xlsh[k * 512 + h * 128 + c]) + xrs[h * 128 + c];
            acc += aws[h * 128 + c] * (v < 0.f ? 0.2f * v : v);
        }
        acc += __shfl_xor_sync(0xffffffffu, acc, 1);
        if (!hf) es[h * 16 + k] = acc;
    }
    __syncthreads();
    if (tid < 4) {
        const int h = tid;
        float m = -1e30f;
        for (int k = 0; k < 16; k++) m = fmaxf(m, es[h * 16 + k]);
        float ex[16], s = 0.f;
        for (int k = 0; k < 16; k++) { ex[k] = expf(es[h * 16 + k] - m); s += ex[k]; }
        for (int k = 0; k < 16; k++) as_[h * 16 + k] = ex[k] / s;
    }
    __syncthreads();
    float o = 0.f;
#pragma unroll
    for (int h = 0; h < 4; h++) {
        float oh = 0.f;
#pragma unroll
        for (int k = 0; k < 16; k++)
            oh += as_[h * 16 + k] * __half2float(xlsh[k * 512 + h * 128 + tid]);
        o += oh;
    }
    g_res[((size_t)fr * NPTS + n) * 128 + tid] = o * 0.25f;
}
__global__ __launch_bounds__(128) void final_kernel(const float* __restrict__ seq, float* __restrict__ out) {
    const int n = blockIdx.x, c = threadIdx.x, b = n >> 12;
    float w = 0.f;
#pragma unroll
    for (int i = 0; i < 4; i++)
        w += g_attn[b * 4 + i] * g_res[((size_t)i * NPTS + n) * 128 + c];
    const float* last = seq + (size_t)4 * NPTS * 128;
    out[(size_t)n * 256 + c] = last[(size_t)n * 128 + c];
    out[(size_t)n * 256 + 128 + c] = w;
}

// ---------------- launch: dist at my #4 (ncu target) ----------------
extern "C" void kernel_launch(void* const* d_in, const int* in_sizes, int n_in,
                              void* d_out, int out_size) {
    (void)in_sizes; (void)n_in; (void)out_size;
    const float* seq = (const float*)d_in[0];
    const float* W1  = (const float*)d_in[1];
    const float* b1  = (const float*)d_in[2];
    const float* W2  = (const float*)d_in[3];
    const float* b2  = (const float*)d_in[4];
    const float* Wl  = (const float*)d_in[5];
    const float* Wr  = (const float*)d_in[6];
    const float* aw  = (const float*)d_in[7];
    float* out = (float*)d_out;

    __half *pw1h, *pw1l, *pw2h, *pw2l, *pwlh, *pwll, *pwrh, *pwrl;
    cudaGetSymbolAddress((void**)&pw1h, g_w1h); cudaGetSymbolAddress((void**)&pw1l, g_w1l);
    cudaGetSymbolAddress((void**)&pw2h, g_w2h); cudaGetSymbolAddress((void**)&pw2l, g_w2l);
    cudaGetSymbolAddress((void**)&pwlh, g_wlh); cudaGetSymbolAddress((void**)&pwll, g_wll);
    cudaGetSymbolAddress((void**)&pwrh, g_wrh); cudaGetSymbolAddress((void**)&pwrl, g_wrl);

    cudaFuncSetAttribute(gf_kernel,   cudaFuncAttributeMaxDynamicSharedMemorySize, GFSM);
    cudaFuncSetAttribute(xlr_kernel,  cudaFuncAttributeMaxDynamicSharedMemorySize, XLSM);
    cudaFuncSetAttribute(dist_kernel, cudaFuncAttributeMaxDynamicSharedMemorySize, DSM);

    split_seq_kernel<<<10240, 256>>>(seq);                       // 1 (incl. gf zero)
    norm_kernel<<<512, 128>>>(seq);                              // 2
    tsplit_kernel<<<dim3(4, 4),  dim3(32, 8)>>>(W1, pw1h, pw1l, 128);   // 3
    dist_kernel<<<dim3(32, 4, 4), 512, DSM>>>();                 // 4 <- ncu target
    topk_kernel<<<8192, 256>>>(seq);                             // 5
    tsplit_kernel<<<dim3(32, 4), dim3(32, 8)>>>(W2, pw2h, pw2l, 1024);
    tsplit_kernel<<<dim3(16, 4), dim3(32, 8)>>>(Wl, pwlh, pwll, 512);
    tsplit_kernel<<<dim3(16, 4), dim3(32, 8)>>>(Wr, pwrh, pwrl, 512);
    gf_kernel<<<640, 512, GFSM>>>(b1, b2);
    attn_kernel<<<1, 512>>>();
    xlr_kernel<<<dim3(128, 5), 512, XLSM>>>();
    gat_kernel<<<dim3(NPTS, 4), 128>>>(aw);
    final_kernel<<<NPTS, 128>>>(seq, out);
}